// round 1
// baseline (speedup 1.0000x reference)
#include <cuda_runtime.h>
#include <math.h>

#define T_STEPS 512
#define BATCH   32
#define HID     1024
#define INP     1024
#define G4H     4096   // 4*HID

// Scratch: precomputed input-side gate projections xg[T*B][4H] (256 MB) and cell state.
__device__ float g_xg[(size_t)T_STEPS * BATCH * G4H];
__device__ float g_c[BATCH * HID];

// ---------------------------------------------------------------------------
// Kernel 1: xg = x @ W^T + (bias_ih + bias_hh)
// M=16384 (T*B), N=4096, K=1024. Both operands row-major, K contiguous (NT GEMM).
// CTA tile 64x64, 256 threads, thread tile 4x4, K-tile 16, smem transposed [k][mn].
// ---------------------------------------------------------------------------
__global__ void gemm_xw_kernel(const float* __restrict__ x,
                               const float* __restrict__ W,
                               const float* __restrict__ bih,
                               const float* __restrict__ bhh) {
    __shared__ float As[16][68];  // As[k][m], pad 68 (272B rows, 16B aligned)
    __shared__ float Bs[16][68];  // Bs[k][n]

    const int tid = threadIdx.x;
    const int tx = tid & 15;        // col group
    const int ty = tid >> 4;        // row group
    const int m0 = blockIdx.y * 64;
    const int n0 = blockIdx.x * 64;

    const int lr = tid >> 2;        // 0..63 tile row to load
    const int lk = (tid & 3) * 4;   // 0,4,8,12

    const float* xA = x + (size_t)(m0 + lr) * INP + lk;
    const float* wB = W + (size_t)(n0 + lr) * INP + lk;

    float acc[4][4] = {};

    for (int k0 = 0; k0 < INP; k0 += 16) {
        float4 av = *(const float4*)(xA + k0);
        float4 bv = *(const float4*)(wB + k0);
        As[lk + 0][lr] = av.x; As[lk + 1][lr] = av.y;
        As[lk + 2][lr] = av.z; As[lk + 3][lr] = av.w;
        Bs[lk + 0][lr] = bv.x; Bs[lk + 1][lr] = bv.y;
        Bs[lk + 2][lr] = bv.z; Bs[lk + 3][lr] = bv.w;
        __syncthreads();

#pragma unroll
        for (int kk = 0; kk < 16; kk++) {
            float4 a = *(const float4*)&As[kk][ty * 4];
            float4 b = *(const float4*)&Bs[kk][tx * 4];
            acc[0][0] += a.x * b.x; acc[0][1] += a.x * b.y; acc[0][2] += a.x * b.z; acc[0][3] += a.x * b.w;
            acc[1][0] += a.y * b.x; acc[1][1] += a.y * b.y; acc[1][2] += a.y * b.z; acc[1][3] += a.y * b.w;
            acc[2][0] += a.z * b.x; acc[2][1] += a.z * b.y; acc[2][2] += a.z * b.z; acc[2][3] += a.z * b.w;
            acc[3][0] += a.w * b.x; acc[3][1] += a.w * b.y; acc[3][2] += a.w * b.z; acc[3][3] += a.w * b.w;
        }
        __syncthreads();
    }

    const float4 bi = *(const float4*)&bih[n0 + tx * 4];
    const float4 bh = *(const float4*)&bhh[n0 + tx * 4];
    const float4 bias = make_float4(bi.x + bh.x, bi.y + bh.y, bi.z + bh.z, bi.w + bh.w);

#pragma unroll
    for (int i = 0; i < 4; i++) {
        float4 v = make_float4(acc[i][0] + bias.x, acc[i][1] + bias.y,
                               acc[i][2] + bias.z, acc[i][3] + bias.w);
        *(float4*)&g_xg[(size_t)(m0 + ty * 4 + i) * G4H + n0 + tx * 4] = v;
    }
}

// ---------------------------------------------------------------------------
// Kernel 2: one LSTM step.
// CTA covers a j-slice of 8 hidden columns ACROSS all 4 gates -> 32 gate columns
// (n = gate*1024 + j0 + jj), all 32 batch rows. 128 CTAs x 256 threads.
// GEMM part: S[32b][32c] = h_{t-1} @ U[cols]^T (K=1024), thread tile 2x2
// (b in {tb, tb+16}, c in {tc, tc+16}), K-tile 32, float4-vectorized.
// Epilogue: g = S + xg[t]; gates; c,h update; h written straight into d_out.
// ---------------------------------------------------------------------------
__global__ void lstm_step_kernel(const float* __restrict__ hprev,
                                 const float* __restrict__ U,
                                 float* __restrict__ hout,
                                 int t) {
    __shared__ float As[32][36];   // h tile  [b][k], 144B rows (16B aligned)
    __shared__ float Bs[32][36];   // U tile  [c_local][k]
    __shared__ float S[32][33];    // gemm result [b][c_local]

    const int tid = threadIdx.x;
    const int tc = tid & 15;       // 0..15
    const int tb = tid >> 4;       // 0..15
    const int j0 = blockIdx.x * 8;

    const int lr = tid >> 3;       // 0..31, tile row to load
    const int lk = (tid & 7) * 4;  // 0..28
    // c_local = lr maps to global gate row n = (lr/8)*H + j0 + (lr%8)
    const int nrow = (lr >> 3) * HID + j0 + (lr & 7);

    float a00 = 0.f, a01 = 0.f, a10 = 0.f, a11 = 0.f;

    if (t > 0) {
        const float* hA = hprev + lr * HID + lk;
        const float* uB = U + (size_t)nrow * HID + lk;
        for (int k0 = 0; k0 < HID; k0 += 32) {
            *(float4*)&As[lr][lk] = *(const float4*)(hA + k0);
            *(float4*)&Bs[lr][lk] = *(const float4*)(uB + k0);
            __syncthreads();
#pragma unroll
            for (int kk = 0; kk < 32; kk += 4) {
                float4 av0 = *(const float4*)&As[tb][kk];
                float4 av1 = *(const float4*)&As[tb + 16][kk];
                float4 bv0 = *(const float4*)&Bs[tc][kk];
                float4 bv1 = *(const float4*)&Bs[tc + 16][kk];
                a00 += av0.x * bv0.x + av0.y * bv0.y + av0.z * bv0.z + av0.w * bv0.w;
                a01 += av0.x * bv1.x + av0.y * bv1.y + av0.z * bv1.z + av0.w * bv1.w;
                a10 += av1.x * bv0.x + av1.y * bv0.y + av1.z * bv0.z + av1.w * bv0.w;
                a11 += av1.x * bv1.x + av1.y * bv1.y + av1.z * bv1.z + av1.w * bv1.w;
            }
            __syncthreads();
        }
    }

    S[tb][tc]           = a00;
    S[tb][tc + 16]      = a01;
    S[tb + 16][tc]      = a10;
    S[tb + 16][tc + 16] = a11;
    __syncthreads();

    // Gate epilogue: one thread per (b, jj) pair; 32*8 = 256 = blockDim.
    const int b  = tid >> 3;
    const int jj = tid & 7;
    const int col = j0 + jj;
    const float* xgt = g_xg + (size_t)t * (BATCH * G4H) + (size_t)b * G4H;

    float gi = S[b][0 * 8 + jj] + xgt[0 * HID + col];
    float gf = S[b][1 * 8 + jj] + xgt[1 * HID + col];
    float gc = S[b][2 * 8 + jj] + xgt[2 * HID + col];
    float go = S[b][3 * 8 + jj] + xgt[3 * HID + col];

    float it = 1.f / (1.f + expf(-gi));
    float ft = 1.f / (1.f + expf(-gf));
    float ch = tanhf(gc);
    float ot = 1.f / (1.f + expf(-go));

    float cold = (t > 0) ? g_c[b * HID + col] : 0.f;
    float ct = ft * cold + it * ch;
    float ht = ot * tanhf(ct);

    g_c[b * HID + col] = ct;
    hout[b * HID + col] = ht;
}

// ---------------------------------------------------------------------------
// Kernel 3: append h_n (= output[T-1]) and c_n to the output buffer.
// ---------------------------------------------------------------------------
__global__ void finalize_kernel(float* __restrict__ out) {
    int i = blockIdx.x * blockDim.x + threadIdx.x;
    const size_t slab = (size_t)BATCH * HID;
    if (i < BATCH * HID) {
        out[(size_t)T_STEPS * slab + i]        = out[(size_t)(T_STEPS - 1) * slab + i];
        out[(size_t)T_STEPS * slab + slab + i] = g_c[i];
    }
}

extern "C" void kernel_launch(void* const* d_in, const int* in_sizes, int n_in,
                              void* d_out, int out_size) {
    const float* x   = (const float*)d_in[0];
    const float* W   = (const float*)d_in[1];
    const float* U   = (const float*)d_in[2];
    const float* bih = (const float*)d_in[3];
    const float* bhh = (const float*)d_in[4];
    float* out = (float*)d_out;

    // Input projection: 16384x4096x1024 NT GEMM
    dim3 gg(G4H / 64, (T_STEPS * BATCH) / 64);   // (64, 256)
    gemm_xw_kernel<<<gg, 256>>>(x, W, bih, bhh);

    // Sequential recurrence: h state lives in the output buffer slabs.
    const size_t slab = (size_t)BATCH * HID;
    for (int t = 0; t < T_STEPS; t++) {
        const float* hprev = (t == 0) ? nullptr : out + (size_t)(t - 1) * slab;
        lstm_step_kernel<<<HID / 8, 256>>>(hprev, U, out + (size_t)t * slab, t);
    }

    finalize_kernel<<<(BATCH * HID + 255) / 256, 256>>>(out);
}

// round 5
// speedup vs baseline: 2.1553x; 2.1553x over previous
#include <cuda_runtime.h>
#include <cuda_bf16.h>
#include <stdint.h>
#include <math.h>

#define T_STEPS 512
#define BATCH   32
#define HID     1024
#define INP     1024
#define G4H     4096

// ---------------- global scratch (no allocations allowed) ----------------
// xg transposed: [t][gate_col(4096)][b(32)] so step-kernel reads are coalesced.
__device__ float g_xg[(size_t)T_STEPS * G4H * BATCH];
__device__ float g_c[HID * BATCH];          // [col][b]
// U packed in per-thread m16n8k16 A-fragment order, bf16 hi/lo:
// unit u (16B) = [jt(128)][w(8)][kt(8)][mt(2)][term(2)][lane(32)]
__device__ __align__(16) unsigned char g_Upk[128u * 8u * 1024u * 16u];   // 16 MB
// h packed in per-thread B-fragment order, bf16 hi/lo, double buffered on t&1:
// unit (8B) = [w(8)][kt(8)][nt(4)][term(2)][lane(32)]
__device__ __align__(16) unsigned char g_hpk[2][8u * 8u * 4u * 2u * 32u * 8u]; // 2 x 128KB

// ---------------------------------------------------------------------------
// Kernel 1: xg = x @ W^T + (bias_ih + bias_hh), output transposed to [t][n][b].
// (validated FFMA GEMM, near fp32 roofline)
// ---------------------------------------------------------------------------
__global__ void gemm_xw_kernel(const float* __restrict__ x,
                               const float* __restrict__ W,
                               const float* __restrict__ bih,
                               const float* __restrict__ bhh) {
    __shared__ float As[16][68];
    __shared__ float Bs[16][68];

    const int tid = threadIdx.x;
    const int tx = tid & 15;
    const int ty = tid >> 4;
    const int m0 = blockIdx.y * 64;
    const int n0 = blockIdx.x * 64;

    const int lr = tid >> 2;
    const int lk = (tid & 3) * 4;

    const float* xA = x + (size_t)(m0 + lr) * INP + lk;
    const float* wB = W + (size_t)(n0 + lr) * INP + lk;

    float acc[4][4] = {};

    for (int k0 = 0; k0 < INP; k0 += 16) {
        float4 av = *(const float4*)(xA + k0);
        float4 bv = *(const float4*)(wB + k0);
        As[lk + 0][lr] = av.x; As[lk + 1][lr] = av.y;
        As[lk + 2][lr] = av.z; As[lk + 3][lr] = av.w;
        Bs[lk + 0][lr] = bv.x; Bs[lk + 1][lr] = bv.y;
        Bs[lk + 2][lr] = bv.z; Bs[lk + 3][lr] = bv.w;
        __syncthreads();

#pragma unroll
        for (int kk = 0; kk < 16; kk++) {
            float4 a = *(const float4*)&As[kk][ty * 4];
            float4 b = *(const float4*)&Bs[kk][tx * 4];
            acc[0][0] += a.x * b.x; acc[0][1] += a.x * b.y; acc[0][2] += a.x * b.z; acc[0][3] += a.x * b.w;
            acc[1][0] += a.y * b.x; acc[1][1] += a.y * b.y; acc[1][2] += a.y * b.z; acc[1][3] += a.y * b.w;
            acc[2][0] += a.z * b.x; acc[2][1] += a.z * b.y; acc[2][2] += a.z * b.z; acc[2][3] += a.z * b.w;
            acc[3][0] += a.w * b.x; acc[3][1] += a.w * b.y; acc[3][2] += a.w * b.z; acc[3][3] += a.w * b.w;
        }
        __syncthreads();
    }

    const float4 bi = *(const float4*)&bih[n0 + tx * 4];
    const float4 bh = *(const float4*)&bhh[n0 + tx * 4];
    const float bias[4] = {bi.x + bh.x, bi.y + bh.y, bi.z + bh.z, bi.w + bh.w};

#pragma unroll
    for (int i = 0; i < 4; i++) {
        int m = m0 + ty * 4 + i;
        int tt = m >> 5, bb = m & 31;
        float* dst = g_xg + ((size_t)tt * G4H + n0 + tx * 4) * BATCH + bb;
#pragma unroll
        for (int jc = 0; jc < 4; jc++)
            dst[jc * BATCH] = acc[i][jc] + bias[jc];
    }
}

// ---------------------------------------------------------------------------
// Kernel 2: pack U into bf16 hi/lo m16n8k16 A-fragment-linear layout.
// Fragment regs (row-major A): R0={ (r,c0),(r,c0+1) }, R1={ r+8 same cols },
// R2={ (r,c0+8),(r,c0+9) }, R3={ r+8, c0+8 }, r = mt*16+lane/4, c0 = (lane%4)*2.
// Local M row rr (0..31) = gate*8 + jj -> U row = gate*1024 + jt*8 + jj.
// ---------------------------------------------------------------------------
__device__ __forceinline__ unsigned short bfh(float f) {
    return __bfloat16_as_ushort(__float2bfloat16(f));
}
__device__ __forceinline__ float bfr(float f) {   // residual after hi
    return f - __bfloat162float(__float2bfloat16(f));
}

__global__ void pack_U_kernel(const float* __restrict__ U) {
    unsigned u = blockIdx.x * blockDim.x + threadIdx.x;   // 1,048,576 units
    int lane = u & 31;
    int term = (u >> 5) & 1;
    int mt   = (u >> 6) & 1;
    int kt   = (u >> 7) & 7;
    int w    = (u >> 10) & 7;
    int jt   = u >> 13;

    int r_lo = mt * 16 + (lane >> 2);
    int r_hi = r_lo + 8;
    int c0   = w * 128 + kt * 16 + (lane & 3) * 2;

    int R0 = (r_lo >> 3) * HID + jt * 8 + (r_lo & 7);
    int R1 = (r_hi >> 3) * HID + jt * 8 + (r_hi & 7);

    float2 aL0 = *(const float2*)(U + (size_t)R0 * INP + c0);
    float2 aL8 = *(const float2*)(U + (size_t)R0 * INP + c0 + 8);
    float2 aH0 = *(const float2*)(U + (size_t)R1 * INP + c0);
    float2 aH8 = *(const float2*)(U + (size_t)R1 * INP + c0 + 8);

    if (term) {  // lo residuals
        aL0.x = bfr(aL0.x); aL0.y = bfr(aL0.y); aL8.x = bfr(aL8.x); aL8.y = bfr(aL8.y);
        aH0.x = bfr(aH0.x); aH0.y = bfr(aH0.y); aH8.x = bfr(aH8.x); aH8.y = bfr(aH8.y);
    }
    uint4 q;
    q.x = (uint32_t)bfh(aL0.x) | ((uint32_t)bfh(aL0.y) << 16);
    q.y = (uint32_t)bfh(aH0.x) | ((uint32_t)bfh(aH0.y) << 16);
    q.z = (uint32_t)bfh(aL8.x) | ((uint32_t)bfh(aL8.y) << 16);
    q.w = (uint32_t)bfh(aH8.x) | ((uint32_t)bfh(aH8.y) << 16);

    ((uint4*)g_Upk)[u] = q;
}

// ---------------------------------------------------------------------------
// Kernel 3: one LSTM step via mma.sync bf16-split + fused gate epilogue.
// grid = 128 (jt: 8 hidden cols x 4 gates = M=32), block = 256 (8 warps).
// Warp w handles K-chunk [w*128, w*128+128); partials reduced through smem.
// ---------------------------------------------------------------------------
__device__ __forceinline__ void mma16816(float* d, const uint32_t* a, const uint32_t* b) {
    asm volatile(
        "mma.sync.aligned.m16n8k16.row.col.f32.bf16.bf16.f32 "
        "{%0,%1,%2,%3}, {%4,%5,%6,%7}, {%8,%9}, {%0,%1,%2,%3};"
        : "+f"(d[0]), "+f"(d[1]), "+f"(d[2]), "+f"(d[3])
        : "r"(a[0]), "r"(a[1]), "r"(a[2]), "r"(a[3]), "r"(b[0]), "r"(b[1]));
}

__global__ void __launch_bounds__(256) lstm_step_hmma(float* __restrict__ hout, int t) {
    __shared__ float Sp[8][32][36];   // per-warp partials, padded
    __shared__ float S2[32][32];      // reduced S[m][b]
    __shared__ float Hs[8][33];       // h staging [jj][b]

    const int tid = threadIdx.x;
    const int w = tid >> 5, lane = tid & 31;
    const int jt = blockIdx.x, j0 = jt * 8;

    if (t > 0) {
        float d[2][4][4] = {};
        const uint4* Ub = (const uint4*)g_Upk + ((size_t)(jt * 8 + w) << 10);
        const uint2* Hb = (const uint2*)g_hpk[(t & 1) ^ 1];

#pragma unroll
        for (int kt = 0; kt < 8; kt++) {
            uint4 A[2][2];   // [mt][term]
#pragma unroll
            for (int mt = 0; mt < 2; mt++) {
#pragma unroll
                for (int tm = 0; tm < 2; tm++)
                    A[mt][tm] = Ub[(((kt * 2 + mt) * 2 + tm) << 5) + lane];
            }
            uint2 Bv[4][2];  // [nt][term]
#pragma unroll
            for (int nt = 0; nt < 4; nt++) {
#pragma unroll
                for (int tm = 0; tm < 2; tm++)
                    Bv[nt][tm] = Hb[((((w * 8 + kt) * 4 + nt) * 2 + tm) << 5) + lane];
            }
#pragma unroll
            for (int mt = 0; mt < 2; mt++) {
#pragma unroll
                for (int nt = 0; nt < 4; nt++) {
                    mma16816(d[mt][nt], (const uint32_t*)&A[mt][0], (const uint32_t*)&Bv[nt][0]);
                    mma16816(d[mt][nt], (const uint32_t*)&A[mt][0], (const uint32_t*)&Bv[nt][1]);
                    mma16816(d[mt][nt], (const uint32_t*)&A[mt][1], (const uint32_t*)&Bv[nt][0]);
                }
            }
        }

        // store partials: D frag: c0,c1 -> row g, col cb,cb+1 ; c2,c3 -> row g+8
        const int g = lane >> 2, cb = (lane & 3) * 2;
#pragma unroll
        for (int mt = 0; mt < 2; mt++) {
#pragma unroll
            for (int nt = 0; nt < 4; nt++) {
                int m = mt * 16 + g, n = nt * 8 + cb;
                Sp[w][m][n]         = d[mt][nt][0];
                Sp[w][m][n + 1]     = d[mt][nt][1];
                Sp[w][m + 8][n]     = d[mt][nt][2];
                Sp[w][m + 8][n + 1] = d[mt][nt][3];
            }
        }
        __syncthreads();

        // reduce over 8 warps: thread owns S[m][n4..n4+3]
        {
            int m = tid >> 3, n4 = (tid & 7) * 4;
            float4 s = *(const float4*)&Sp[0][m][n4];
#pragma unroll
            for (int ww = 1; ww < 8; ww++) {
                float4 p = *(const float4*)&Sp[ww][m][n4];
                s.x += p.x; s.y += p.y; s.z += p.z; s.w += p.w;
            }
            *(float4*)&S2[m][n4] = s;
        }
        __syncthreads();
    }

    // ---- phase 1: gates + state update; thread = (jj = tid>>5, b = tid&31) ----
    {
        const int jj = tid >> 5, b = tid & 31;
        const int col = j0 + jj;
        const float* xb = g_xg + (size_t)t * G4H * BATCH;
        float gi = xb[(size_t)(0 * HID + col) * BATCH + b];
        float gf = xb[(size_t)(1 * HID + col) * BATCH + b];
        float gc = xb[(size_t)(2 * HID + col) * BATCH + b];
        float go = xb[(size_t)(3 * HID + col) * BATCH + b];
        float cold = 0.f;
        if (t > 0) {
            gi += S2[0  + jj][b];
            gf += S2[8  + jj][b];
            gc += S2[16 + jj][b];
            go += S2[24 + jj][b];
            cold = g_c[col * BATCH + b];
        }
        float it = 1.f / (1.f + expf(-gi));
        float ft = 1.f / (1.f + expf(-gf));
        float ch = tanhf(gc);
        float ot = 1.f / (1.f + expf(-go));
        float ct = ft * cold + it * ch;
        float ht = ot * tanhf(ct);
        g_c[col * BATCH + b] = ct;
        Hs[jj][b] = ht;
    }
    __syncthreads();

    // ---- phase 2a: h output (thread = (b = tid>>3, jj = tid&7)) ----
    {
        int b = tid >> 3, jj = tid & 7;
        hout[(size_t)b * HID + j0 + jj] = Hs[jj][b];
    }
    // ---- phase 2b: B-fragment pack (thread = (b, pair p, term)) ----
    {
        int b = tid >> 3, p = (tid >> 1) & 3, term = tid & 1;
        int c = j0 + 2 * p;
        float v0 = Hs[2 * p][b], v1 = Hs[2 * p + 1][b];
        if (term) { v0 = bfr(v0); v1 = bfr(v1); }
        uint32_t pk = (uint32_t)bfh(v0) | ((uint32_t)bfh(v1) << 16);
        int ww = c >> 7, kt = (c >> 4) & 7, nt = b >> 3;
        int tf = (b & 7) * 4 + ((c & 7) >> 1);
        int q  = (c >> 3) & 1;
        unsigned char* dst = g_hpk[t & 1] +
            ((size_t)((((ww * 8 + kt) * 4 + nt) * 2 + term) * 32 + tf) << 3) + q * 4;
        *(uint32_t*)dst = pk;
    }
}

// ---------------------------------------------------------------------------
// Kernel 4: append h_n and c_n (c_n transposed back from [col][b]).
// ---------------------------------------------------------------------------
__global__ void finalize_kernel(float* __restrict__ out) {
    int i = blockIdx.x * blockDim.x + threadIdx.x;
    const size_t slab = (size_t)BATCH * HID;
    if (i < BATCH * HID) {
        int bb = i / HID, col = i % HID;
        out[(size_t)T_STEPS * slab + i]       = out[(size_t)(T_STEPS - 1) * slab + i];
        out[(size_t)(T_STEPS + 1) * slab + i] = g_c[col * BATCH + bb];
    }
}

extern "C" void kernel_launch(void* const* d_in, const int* in_sizes, int n_in,
                              void* d_out, int out_size) {
    const float* x   = (const float*)d_in[0];
    const float* W   = (const float*)d_in[1];
    const float* U   = (const float*)d_in[2];
    const float* bih = (const float*)d_in[3];
    const float* bhh = (const float*)d_in[4];
    float* out = (float*)d_out;

    pack_U_kernel<<<4096, 256>>>(U);

    dim3 gg(G4H / 64, (T_STEPS * BATCH) / 64);
    gemm_xw_kernel<<<gg, 256>>>(x, W, bih, bhh);

    const size_t slab = (size_t)BATCH * HID;
    for (int t = 0; t < T_STEPS; t++)
        lstm_step_hmma<<<128, 256>>>(out + (size_t)t * slab, t);

    finalize_kernel<<<(BATCH * HID + 255) / 256, 256>>>(out);
}

// round 7
// speedup vs baseline: 3.2645x; 1.5146x over previous
#include <cuda_runtime.h>
#include <cuda_bf16.h>
#include <stdint.h>
#include <math.h>

#define T_STEPS 512
#define BATCH   32
#define HID     1024
#define INP     1024
#define G4H     4096

// ---------------- global scratch (no allocations allowed) ----------------
// xg transposed: [t][gate_col(4096)][b(32)] so step-kernel reads are coalesced.
__device__ float g_xg[(size_t)T_STEPS * G4H * BATCH];
__device__ float g_c[HID * BATCH];          // [col][b]
// U packed in per-thread m16n8k16 A-fragment order, bf16 hi/lo:
// unit u (16B) = [jt(128)][w(8)][kt(8)][mt(2)][term(2)][lane(32)]
__device__ __align__(16) unsigned char g_Upk[128u * 8u * 1024u * 16u];   // 16 MB
// h packed in per-thread B-fragment order, bf16 hi/lo, double buffered on t&1:
// unit (8B) = [w(8)][kt(8)][nt(4)][term(2)][lane(32)]
__device__ __align__(16) unsigned char g_hpk[2][8u * 8u * 4u * 2u * 32u * 8u]; // 2 x 128KB
// x packed in A-fragment order: unit u (16B) = [m16(1024)][kt(64)][term(2)][lane(32)]
__device__ __align__(16) unsigned char g_xpk[1024u * 64u * 2u * 32u * 16u];    // 64 MB
// W packed in B-fragment order: unit u (8B) = [n8(512)][kt(64)][term(2)][lane(32)]
__device__ __align__(16) unsigned char g_Wpk[512u * 64u * 2u * 32u * 8u];      // 16 MB

__device__ __forceinline__ unsigned short bfh(float f) {
    return __bfloat16_as_ushort(__float2bfloat16(f));
}
__device__ __forceinline__ float bfr(float f) {   // residual after hi
    return f - __bfloat162float(__float2bfloat16(f));
}
__device__ __forceinline__ void mma16816(float* d, const uint32_t* a, const uint32_t* b) {
    asm volatile(
        "mma.sync.aligned.m16n8k16.row.col.f32.bf16.bf16.f32 "
        "{%0,%1,%2,%3}, {%4,%5,%6,%7}, {%8,%9}, {%0,%1,%2,%3};"
        : "+f"(d[0]), "+f"(d[1]), "+f"(d[2]), "+f"(d[3])
        : "r"(a[0]), "r"(a[1]), "r"(a[2]), "r"(a[3]), "r"(b[0]), "r"(b[1]));
}

// ---------------------------------------------------------------------------
// Kernel 1a: pack x into bf16 hi/lo A-fragment-linear layout (one-time).
// A frag (m16n8k16 row-major): q.x=(r,c0|c0+1) q.y=(r+8,..) q.z=(r,c0+8|9) q.w=(r+8,c0+8|9)
// with r = lane>>2, c0 = kt*16 + (lane&3)*2.
// ---------------------------------------------------------------------------
__global__ void pack_x_kernel(const float* __restrict__ x) {
    unsigned u = blockIdx.x * blockDim.x + threadIdx.x;   // 4,194,304 units
    int lane = u & 31;
    int term = (u >> 5) & 1;
    int kt   = (u >> 6) & 63;
    int m16  = u >> 12;

    int m_lo = m16 * 16 + (lane >> 2);
    int c0   = kt * 16 + (lane & 3) * 2;

    float2 aL0 = *(const float2*)(x + (size_t)m_lo * INP + c0);
    float2 aL8 = *(const float2*)(x + (size_t)m_lo * INP + c0 + 8);
    float2 aH0 = *(const float2*)(x + (size_t)(m_lo + 8) * INP + c0);
    float2 aH8 = *(const float2*)(x + (size_t)(m_lo + 8) * INP + c0 + 8);

    if (term) {
        aL0.x = bfr(aL0.x); aL0.y = bfr(aL0.y); aL8.x = bfr(aL8.x); aL8.y = bfr(aL8.y);
        aH0.x = bfr(aH0.x); aH0.y = bfr(aH0.y); aH8.x = bfr(aH8.x); aH8.y = bfr(aH8.y);
    }
    uint4 q;
    q.x = (uint32_t)bfh(aL0.x) | ((uint32_t)bfh(aL0.y) << 16);
    q.y = (uint32_t)bfh(aH0.x) | ((uint32_t)bfh(aH0.y) << 16);
    q.z = (uint32_t)bfh(aL8.x) | ((uint32_t)bfh(aL8.y) << 16);
    q.w = (uint32_t)bfh(aH8.x) | ((uint32_t)bfh(aH8.y) << 16);
    ((uint4*)g_xpk)[u] = q;
}

// ---------------------------------------------------------------------------
// Kernel 1b: pack W into bf16 hi/lo B-fragment-linear layout (one-time).
// B frag (col-major k x n): lane = (n%8)*4 + (k%8)/2; reg0 = k pair, reg1 = k+8 pair.
// ---------------------------------------------------------------------------
__global__ void pack_W_kernel(const float* __restrict__ W) {
    unsigned u = blockIdx.x * blockDim.x + threadIdx.x;   // 2,097,152 units
    int lane = u & 31;
    int term = (u >> 5) & 1;
    int kt   = (u >> 6) & 63;
    int n8   = u >> 12;

    int n  = n8 * 8 + (lane >> 2);
    int k0 = kt * 16 + (lane & 3) * 2;

    float2 b0 = *(const float2*)(W + (size_t)n * INP + k0);
    float2 b1 = *(const float2*)(W + (size_t)n * INP + k0 + 8);
    if (term) { b0.x = bfr(b0.x); b0.y = bfr(b0.y); b1.x = bfr(b1.x); b1.y = bfr(b1.y); }
    uint2 q;
    q.x = (uint32_t)bfh(b0.x) | ((uint32_t)bfh(b0.y) << 16);
    q.y = (uint32_t)bfh(b1.x) | ((uint32_t)bfh(b1.y) << 16);
    ((uint2*)g_Wpk)[u] = q;
}

// ---------------------------------------------------------------------------
// Kernel 1c: xg = x @ W^T + bias via HMMA bf16-split, fragment-direct.
// Warp tile 64x64. 8 warps/CTA share an mtile (L1 reuse of A frags).
// grid = 2048: wtile = bx*8+w; mtile = wtile>>6 (256), ntile = wtile&63 (64).
// Epilogue adds bias and writes transposed [t][n][b].
// ---------------------------------------------------------------------------
__global__ void __launch_bounds__(256) gemm_xw_hmma(const float* __restrict__ bih,
                                                    const float* __restrict__ bhh) {
    const int w = threadIdx.x >> 5, lane = threadIdx.x & 31;
    const unsigned wtile = blockIdx.x * 8 + w;
    const int mtile = wtile >> 6;        // 64-row block of m
    const int ntile = wtile & 63;        // 64-col block of n

    float d[4][8][4] = {};
    const uint4* Xp = (const uint4*)g_xpk;
    const uint2* Wp = (const uint2*)g_Wpk;

    for (int kt = 0; kt < 64; kt++) {
        uint4 A[4][2];
#pragma unroll
        for (int mf = 0; mf < 4; mf++) {
            unsigned m16 = mtile * 4 + mf;
#pragma unroll
            for (int tm = 0; tm < 2; tm++)
                A[mf][tm] = Xp[(((m16 * 64u + kt) * 2u + tm) << 5) + lane];
        }
        uint2 Bv[8][2];
#pragma unroll
        for (int nf = 0; nf < 8; nf++) {
            unsigned n8 = ntile * 8 + nf;
#pragma unroll
            for (int tm = 0; tm < 2; tm++)
                Bv[nf][tm] = Wp[(((n8 * 64u + kt) * 2u + tm) << 5) + lane];
        }
#pragma unroll
        for (int mf = 0; mf < 4; mf++) {
#pragma unroll
            for (int nf = 0; nf < 8; nf++) {
                mma16816(d[mf][nf], (const uint32_t*)&A[mf][0], (const uint32_t*)&Bv[nf][0]);
                mma16816(d[mf][nf], (const uint32_t*)&A[mf][0], (const uint32_t*)&Bv[nf][1]);
                mma16816(d[mf][nf], (const uint32_t*)&A[mf][1], (const uint32_t*)&Bv[nf][0]);
            }
        }
    }

    // Epilogue: D frag -> (m = mtile*64 + mf*16 + g [+8], n = ntile*64 + nf*8 + cb [+1])
    const int g = lane >> 2, cb = (lane & 3) * 2;
#pragma unroll
    for (int nf = 0; nf < 8; nf++) {
        int n = ntile * 64 + nf * 8 + cb;
        float bs0 = bih[n] + bhh[n];
        float bs1 = bih[n + 1] + bhh[n + 1];
#pragma unroll
        for (int mf = 0; mf < 4; mf++) {
            int m0 = mtile * 64 + mf * 16 + g;
            int t0 = m0 >> 5, b0 = m0 & 31;
            int m1 = m0 + 8;
            int t1 = m1 >> 5, b1 = m1 & 31;
            float* p0 = g_xg + ((size_t)t0 * G4H + n) * BATCH + b0;
            float* p1 = g_xg + ((size_t)t1 * G4H + n) * BATCH + b1;
            p0[0]     = d[mf][nf][0] + bs0;
            p0[BATCH] = d[mf][nf][1] + bs1;
            p1[0]     = d[mf][nf][2] + bs0;
            p1[BATCH] = d[mf][nf][3] + bs1;
        }
    }
}

// ---------------------------------------------------------------------------
// Kernel 2: pack U into bf16 hi/lo m16n8k16 A-fragment-linear layout.
// ---------------------------------------------------------------------------
__global__ void pack_U_kernel(const float* __restrict__ U) {
    unsigned u = blockIdx.x * blockDim.x + threadIdx.x;   // 1,048,576 units
    int lane = u & 31;
    int term = (u >> 5) & 1;
    int mt   = (u >> 6) & 1;
    int kt   = (u >> 7) & 7;
    int w    = (u >> 10) & 7;
    int jt   = u >> 13;

    int r_lo = mt * 16 + (lane >> 2);
    int r_hi = r_lo + 8;
    int c0   = w * 128 + kt * 16 + (lane & 3) * 2;

    int R0 = (r_lo >> 3) * HID + jt * 8 + (r_lo & 7);
    int R1 = (r_hi >> 3) * HID + jt * 8 + (r_hi & 7);

    float2 aL0 = *(const float2*)(U + (size_t)R0 * INP + c0);
    float2 aL8 = *(const float2*)(U + (size_t)R0 * INP + c0 + 8);
    float2 aH0 = *(const float2*)(U + (size_t)R1 * INP + c0);
    float2 aH8 = *(const float2*)(U + (size_t)R1 * INP + c0 + 8);

    if (term) {  // lo residuals
        aL0.x = bfr(aL0.x); aL0.y = bfr(aL0.y); aL8.x = bfr(aL8.x); aL8.y = bfr(aL8.y);
        aH0.x = bfr(aH0.x); aH0.y = bfr(aH0.y); aH8.x = bfr(aH8.x); aH8.y = bfr(aH8.y);
    }
    uint4 q;
    q.x = (uint32_t)bfh(aL0.x) | ((uint32_t)bfh(aL0.y) << 16);
    q.y = (uint32_t)bfh(aH0.x) | ((uint32_t)bfh(aH0.y) << 16);
    q.z = (uint32_t)bfh(aL8.x) | ((uint32_t)bfh(aL8.y) << 16);
    q.w = (uint32_t)bfh(aH8.x) | ((uint32_t)bfh(aH8.y) << 16);

    ((uint4*)g_Upk)[u] = q;
}

// ---------------------------------------------------------------------------
// Kernel 3: one LSTM step via mma.sync bf16-split + fused gate epilogue.
// grid = 128 (jt: 8 hidden cols x 4 gates = M=32), block = 256 (8 warps).
// Warp w handles K-chunk [w*128, w*128+128); partials reduced through smem.
// ---------------------------------------------------------------------------
__global__ void __launch_bounds__(256) lstm_step_hmma(float* __restrict__ hout, int t) {
    __shared__ float Sp[8][32][36];   // per-warp partials, padded
    __shared__ float S2[32][32];      // reduced S[m][b]
    __shared__ float Hs[8][33];       // h staging [jj][b]

    const int tid = threadIdx.x;
    const int w = tid >> 5, lane = tid & 31;
    const int jt = blockIdx.x, j0 = jt * 8;

    if (t > 0) {
        float d[2][4][4] = {};
        const uint4* Ub = (const uint4*)g_Upk + ((size_t)(jt * 8 + w) << 10);
        const uint2* Hb = (const uint2*)g_hpk[(t & 1) ^ 1];

#pragma unroll
        for (int kt = 0; kt < 8; kt++) {
            uint4 A[2][2];   // [mt][term]
#pragma unroll
            for (int mt = 0; mt < 2; mt++) {
#pragma unroll
                for (int tm = 0; tm < 2; tm++)
                    A[mt][tm] = Ub[(((kt * 2 + mt) * 2 + tm) << 5) + lane];
            }
            uint2 Bv[4][2];  // [nt][term]
#pragma unroll
            for (int nt = 0; nt < 4; nt++) {
#pragma unroll
                for (int tm = 0; tm < 2; tm++)
                    Bv[nt][tm] = Hb[((((w * 8 + kt) * 4 + nt) * 2 + tm) << 5) + lane];
            }
#pragma unroll
            for (int mt = 0; mt < 2; mt++) {
#pragma unroll
                for (int nt = 0; nt < 4; nt++) {
                    mma16816(d[mt][nt], (const uint32_t*)&A[mt][0], (const uint32_t*)&Bv[nt][0]);
                    mma16816(d[mt][nt], (const uint32_t*)&A[mt][0], (const uint32_t*)&Bv[nt][1]);
                    mma16816(d[mt][nt], (const uint32_t*)&A[mt][1], (const uint32_t*)&Bv[nt][0]);
                }
            }
        }

        // store partials: D frag: c0,c1 -> row g, col cb,cb+1 ; c2,c3 -> row g+8
        const int g = lane >> 2, cb = (lane & 3) * 2;
#pragma unroll
        for (int mt = 0; mt < 2; mt++) {
#pragma unroll
            for (int nt = 0; nt < 4; nt++) {
                int m = mt * 16 + g, n = nt * 8 + cb;
                Sp[w][m][n]         = d[mt][nt][0];
                Sp[w][m][n + 1]     = d[mt][nt][1];
                Sp[w][m + 8][n]     = d[mt][nt][2];
                Sp[w][m + 8][n + 1] = d[mt][nt][3];
            }
        }
        __syncthreads();

        // reduce over 8 warps: thread owns S[m][n4..n4+3]
        {
            int m = tid >> 3, n4 = (tid & 7) * 4;
            float4 s = *(const float4*)&Sp[0][m][n4];
#pragma unroll
            for (int ww = 1; ww < 8; ww++) {
                float4 p = *(const float4*)&Sp[ww][m][n4];
                s.x += p.x; s.y += p.y; s.z += p.z; s.w += p.w;
            }
            *(float4*)&S2[m][n4] = s;
        }
        __syncthreads();
    }

    // ---- phase 1: gates + state update; thread = (jj = tid>>5, b = tid&31) ----
    {
        const int jj = tid >> 5, b = tid & 31;
        const int col = j0 + jj;
        const float* xb = g_xg + (size_t)t * G4H * BATCH;
        float gi = xb[(size_t)(0 * HID + col) * BATCH + b];
        float gf = xb[(size_t)(1 * HID + col) * BATCH + b];
        float gc = xb[(size_t)(2 * HID + col) * BATCH + b];
        float go = xb[(size_t)(3 * HID + col) * BATCH + b];
        float cold = 0.f;
        if (t > 0) {
            gi += S2[0  + jj][b];
            gf += S2[8  + jj][b];
            gc += S2[16 + jj][b];
            go += S2[24 + jj][b];
            cold = g_c[col * BATCH + b];
        }
        float it = 1.f / (1.f + expf(-gi));
        float ft = 1.f / (1.f + expf(-gf));
        float ch = tanhf(gc);
        float ot = 1.f / (1.f + expf(-go));
        float ct = ft * cold + it * ch;
        float ht = ot * tanhf(ct);
        g_c[col * BATCH + b] = ct;
        Hs[jj][b] = ht;
    }
    __syncthreads();

    // ---- phase 2a: h output (thread = (b = tid>>3, jj = tid&7)) ----
    {
        int b = tid >> 3, jj = tid & 7;
        hout[(size_t)b * HID + j0 + jj] = Hs[jj][b];
    }
    // ---- phase 2b: B-fragment pack (thread = (b, pair p, term)) ----
    {
        int b = tid >> 3, p = (tid >> 1) & 3, term = tid & 1;
        int c = j0 + 2 * p;
        float v0 = Hs[2 * p][b], v1 = Hs[2 * p + 1][b];
        if (term) { v0 = bfr(v0); v1 = bfr(v1); }
        uint32_t pk = (uint32_t)bfh(v0) | ((uint32_t)bfh(v1) << 16);
        int ww = c >> 7, kt = (c >> 4) & 7, nt = b >> 3;
        int tf = (b & 7) * 4 + ((c & 7) >> 1);
        int q  = (c >> 3) & 1;
        unsigned char* dst = g_hpk[t & 1] +
            ((size_t)((((ww * 8 + kt) * 4 + nt) * 2 + term) * 32 + tf) << 3) + q * 4;
        *(uint32_t*)dst = pk;
    }
}

// ---------------------------------------------------------------------------
// Kernel 4: append h_n and c_n (c_n transposed back from [col][b]).
// ---------------------------------------------------------------------------
__global__ void finalize_kernel(float* __restrict__ out) {
    int i = blockIdx.x * blockDim.x + threadIdx.x;
    const size_t slab = (size_t)BATCH * HID;
    if (i < BATCH * HID) {
        int bb = i / HID, col = i % HID;
        out[(size_t)T_STEPS * slab + i]       = out[(size_t)(T_STEPS - 1) * slab + i];
        out[(size_t)(T_STEPS + 1) * slab + i] = g_c[col * BATCH + bb];
    }
}

extern "C" void kernel_launch(void* const* d_in, const int* in_sizes, int n_in,
                              void* d_out, int out_size) {
    const float* x   = (const float*)d_in[0];
    const float* W   = (const float*)d_in[1];
    const float* U   = (const float*)d_in[2];
    const float* bih = (const float*)d_in[3];
    const float* bhh = (const float*)d_in[4];
    float* out = (float*)d_out;

    pack_x_kernel<<<16384, 256>>>(x);
    pack_W_kernel<<<8192, 256>>>(W);
    pack_U_kernel<<<4096, 256>>>(U);

    gemm_xw_hmma<<<2048, 256>>>(bih, bhh);

    const size_t slab = (size_t)BATCH * HID;
    for (int t = 0; t < T_STEPS; t++)
        lstm_step_hmma<<<128, 256>>>(out + (size_t)t * slab, t);

    finalize_kernel<<<(BATCH * HID + 255) / 256, 256>>>(out);
}